// round 15
// baseline (speedup 1.0000x reference)
#include <cuda_runtime.h>
#include <cuda_fp16.h>
#include <stdint.h>

#define THREADS 512

// ---------------- weights (pre-transposed fp16: Wt[n][k], k contiguous) ----
__device__ __half g_Wt1[384 * 384];
__device__ __half g_Wt2[192 * 384];
__device__ __half g_Wt3[192 * 192];
// Precomputed dst projection: U[s][n] = b1[n] + sincos(pos[s]) @ W1_bot
__device__ float g_U[16384 * 384];

__global__ void prep_weights(const float* __restrict__ W1,
                             const float* __restrict__ W2,
                             const float* __restrict__ W3) {
    int idx = blockIdx.x * blockDim.x + threadIdx.x;
    const int N1 = 384 * 384, N2 = 192 * 384, N3 = 192 * 192;
    if (idx < N1) {
        int n = idx / 384, k = idx % 384;
        g_Wt1[idx] = __float2half(W1[k * 384 + n]);
    } else if (idx < N1 + N2) {
        int i = idx - N1;
        int n = i / 384, k = i % 384;
        g_Wt2[i] = __float2half(W2[k * 192 + n]);
    } else if (idx < N1 + N2 + N3) {
        int i = idx - N1 - N2;
        int n = i / 192, k = i % 192;
        g_Wt3[i] = __float2half(W3[k * 192 + n]);
    }
}

// ---------------- smem layout (bytes), 128-edge tile, 1 CTA/SM -------------
//   sSrc : half[128*200]  @ 0        (51200)  src embeds / h2, stride 200
//   sH1  : half[128*392]  @ 51200    (100352) layer1 out, stride 392
//          (float[128*196] overlays this region for layer3 fp32 out)
//   sW   : half[2*192*72] @ 151552   (55296)  double-buffered K=64 W chunks
//   sU   : float[8*384]   @ 206848   (12288)  U rows for this tile's 8 groups
//   sOm  : float[32]      @ 219136   (128)    omega table (kills per-elt exp2f)
// Total 219264 B -> 1 CTA / SM.
// Strides 200/392/72 halves ≡ 4 mod 8 words -> conflict-free ldmatrix.
//
// Stage-buffer PARITY DISCIPLINE: running parity `stp` rotates across passes;
// pass chunk c lives in buffer (stp+c)&1, next pass chunk-0 at (stp+nCh)&1 —
// never the buffer the previous pass's LAST chunk was read from.
#define OFF_SRC 0
#define OFF_H1  51200
#define OFF_W   151552
#define OFF_U   206848
#define OFF_OM  219136
#define SMEM_TOTAL 219264
#define W_STAGE 13824   // halves per stage buffer (192*72)

__device__ __forceinline__ uint32_t smem_u32(const void* p) {
    return (uint32_t)__cvta_generic_to_shared(p);
}
__device__ __forceinline__ void ldsm_x4(uint32_t r[4], const __half* p) {
    uint32_t a = smem_u32(p);
    asm volatile("ldmatrix.sync.aligned.m8n8.x4.shared.b16 {%0,%1,%2,%3}, [%4];\n"
                 : "=r"(r[0]), "=r"(r[1]), "=r"(r[2]), "=r"(r[3]) : "r"(a));
}
__device__ __forceinline__ void cp16(void* dst, const void* src) {
    uint32_t s = smem_u32(dst);
    asm volatile("cp.async.cg.shared.global [%0], [%1], 16;\n" :: "r"(s), "l"(src));
}
#define CP_COMMIT() asm volatile("cp.async.commit_group;\n")
#define CP_WAIT0()  asm volatile("cp.async.wait_group 0;\n" ::: "memory")

// fast exact gelu: x * Phi(x), Phi via A&S 7.1.25 erf (|err| ~1e-4, << fp16 noise)
__device__ __forceinline__ float gelu1(float x) {
    float q = fabsf(x) * 0.7071067811865476f;
    float t = __fdividef(1.0f, fmaf(0.47047f, q, 1.0f));
    float poly = t * fmaf(t, fmaf(t, 0.7478556f, -0.0958798f), 0.3480242f);
    float E = poly * __expf(-q * q);              // 1 - erf(q), q >= 0
    float phi = (x >= 0.f) ? fmaf(-0.5f, E, 1.0f) : (0.5f * E);
    return x * phi;
}

// Stage one 64-wide K chunk of Wt[nBase..+192)[kc..kc+64) into stage buffer st.
__device__ __forceinline__ void stage_chunk(char* smem, int tid,
                                            const __half* gW, int ldW,
                                            int nBase, int kc, int st) {
    __half* dst = (__half*)(smem + OFF_W) + st * W_STAGE;
    const __half* src = gW + (size_t)nBase * ldW + kc;
#pragma unroll
    for (int it = 0; it < 3; it++) {
        int i = tid + it * THREADS;      // 0..1535 = 192 rows x 8 16B units
        int rw = i >> 3, v = i & 7;
        cp16(dst + rw * 72 + v * 8, src + (size_t)rw * ldW + v * 8);
    }
    CP_COMMIT();
}

// Core GEMM: C[128x192] = A[128xK] @ Wt[nBase..+192)^T.
// Chunk-0 already committed into buffer (stp&1).
// 16 warps as 4x4 grid of 32x48 warp tiles; K=64 chunks, double-buffered.
// SINGLE-VARIABLE CHANGE vs R11: explicit fragment double-buffering —
// LDSMs for kstep ks+1 issue before the HMMA block of ks, so the smem
// crossbar overlaps the tensor pipe instead of alternating bursts.
__device__ __forceinline__ void mma_core(char* smem, int tid, int lane,
                                         int rowBase, int colBase,
                                         const __half* gW, int ldW, int nBase,
                                         int K, const __half* A, int strideA,
                                         int stp, float (&C)[2][6][4]) {
    const int arow = (lane & 7) + ((lane >> 3) & 1) * 8;
    const int akof = (lane >> 4) * 8;
    const int brow = (lane & 7) + (lane >> 4) * 8;
    const int bkof = ((lane >> 3) & 1) * 8;
    __half* sW = (__half*)(smem + OFF_W);
    const int nCh = K >> 6;
#pragma unroll
    for (int mf = 0; mf < 2; mf++)
#pragma unroll
        for (int nf = 0; nf < 6; nf++)
#pragma unroll
            for (int q = 0; q < 4; q++) C[mf][nf][q] = 0.f;

    for (int c = 0; c < nCh; c++) {
        CP_WAIT0();
        __syncthreads();    // chunk c resident everywhere; all warps done c-1
        if (c + 1 < nCh)
            stage_chunk(smem, tid, gW, ldW, nBase, (c + 1) * 64,
                        (c + 1 + stp) & 1);
        const __half* Wb = sW + ((c + stp) & 1) * W_STAGE;

        uint32_t a[2][2][4], b[2][3][4];
        // prologue: fragments for ks = 0
#pragma unroll
        for (int mf = 0; mf < 2; mf++)
            ldsm_x4(a[0][mf],
                    A + (rowBase + mf * 16 + arow) * strideA + c * 64 + akof);
#pragma unroll
        for (int np = 0; np < 3; np++)
            ldsm_x4(b[0][np], Wb + (colBase + np * 16 + brow) * 72 + bkof);

#pragma unroll
        for (int ks = 0; ks < 4; ks++) {
            int cur = ks & 1, nxt = cur ^ 1;
            if (ks < 3) {   // prefetch ks+1 fragments (overlaps HMMA below)
                int kb = c * 64 + (ks + 1) * 16;
#pragma unroll
                for (int mf = 0; mf < 2; mf++)
                    ldsm_x4(a[nxt][mf],
                            A + (rowBase + mf * 16 + arow) * strideA + kb + akof);
#pragma unroll
                for (int np = 0; np < 3; np++)
                    ldsm_x4(b[nxt][np],
                            Wb + (colBase + np * 16 + brow) * 72 +
                            (ks + 1) * 16 + bkof);
            }
#pragma unroll
            for (int np = 0; np < 3; np++) {
#pragma unroll
                for (int h = 0; h < 2; h++) {
                    int nf = np * 2 + h;
#pragma unroll
                    for (int mf = 0; mf < 2; mf++) {
                        asm volatile(
                            "mma.sync.aligned.m16n8k16.row.col.f32.f16.f16.f32 "
                            "{%0,%1,%2,%3}, {%4,%5,%6,%7}, {%8,%9}, {%0,%1,%2,%3};\n"
                            : "+f"(C[mf][nf][0]), "+f"(C[mf][nf][1]),
                              "+f"(C[mf][nf][2]), "+f"(C[mf][nf][3])
                            : "r"(a[cur][mf][0]), "r"(a[cur][mf][1]),
                              "r"(a[cur][mf][2]), "r"(a[cur][mf][3]),
                              "r"(b[cur][np][h * 2]), "r"(b[cur][np][h * 2 + 1]));
                    }
                }
            }
        }
    }
}

// Epilogue to fp16 smem: out = [gelu](C + bias[(row>>4)*gStride + col]).
__device__ __forceinline__ void epi_half(int lane, int rowBase, int colBase,
                                         float (&C)[2][6][4],
                                         const float* __restrict__ bias,
                                         int gStride, bool doGelu,
                                         __half* outH, int strideOutH,
                                         int outColBase) {
    const int grp = lane >> 2, tig = lane & 3;
#pragma unroll
    for (int mf = 0; mf < 2; mf++) {
        int r0 = rowBase + mf * 16 + grp;
        int r1 = r0 + 8;
        const float* bp = bias + ((rowBase + mf * 16) >> 4) * gStride;
#pragma unroll
        for (int nf = 0; nf < 6; nf++) {
            int cl = colBase + nf * 8 + tig * 2;
            float bv0 = bp[cl], bv1 = bp[cl + 1];
            float v00 = C[mf][nf][0] + bv0;
            float v01 = C[mf][nf][1] + bv1;
            float v10 = C[mf][nf][2] + bv0;
            float v11 = C[mf][nf][3] + bv1;
            if (doGelu) {
                v00 = gelu1(v00); v01 = gelu1(v01);
                v10 = gelu1(v10); v11 = gelu1(v11);
            }
            *(__half2*)(outH + r0 * strideOutH + outColBase + cl) =
                __floats2half2_rn(v00, v01);
            *(__half2*)(outH + r1 * strideOutH + outColBase + cl) =
                __floats2half2_rn(v10, v11);
        }
    }
}

// omega_j = 10000^(-j/32) = 2^(-j*log2(1e4)/32)
#define NLOG (-0.41524101186092033f)

// ---------------- dst projection pre-kernel --------------------------------
// U[s][0..383] = b1 + sincos(pos[s]) @ W1_bot  for s = 0..16383.
// 128 CTAs x 128 rows; same MMA machinery (K=192, two N=192 passes).
__global__ __launch_bounds__(THREADS, 1)
void dst_proj(const float* __restrict__ pos, const float* __restrict__ b1) {
    extern __shared__ char smem[];
    __half* sSrc = (__half*)(smem + OFF_SRC);
    const int tile = blockIdx.x;
    const int tid  = threadIdx.x;
    const int lane = tid & 31;
    const int wid  = tid >> 5;
    const int rowBase = (wid >> 2) * 32;
    const int colBase = (wid & 3) * 48;

    int stp = 0;
    stage_chunk(smem, tid, g_Wt1 + 192, 384, 0, 0, stp);    // W1_bot chunk0

    for (int i = tid; i < 128 * 96; i += THREADS) {
        int r = i / 96, q = i - r * 96;
        int d = q >> 5, j = q & 31;
        int node = tile * 128 + r;
        float x = pos[node * 3 + d] * exp2f((float)j * NLOG);
        sSrc[r * 200 + d * 64 + j]      = __float2half(__sinf(x));
        sSrc[r * 200 + d * 64 + 32 + j] = __float2half(__cosf(x));
    }

    float C[2][6][4];
    const int grp = lane >> 2, tig = lane & 3;
#pragma unroll
    for (int half = 0; half < 2; half++) {
        int nBase = half * 192;
        mma_core(smem, tid, lane, rowBase, colBase, g_Wt1 + 192, 384, nBase,
                 192, sSrc, 200, stp, C);
        stp = (stp + 3) & 1;                   // nCh = 3
        if (half == 0)
            stage_chunk(smem, tid, g_Wt1 + 192, 384, 192, 0, stp);
#pragma unroll
        for (int mf = 0; mf < 2; mf++) {
            int r0 = rowBase + mf * 16 + grp;
            int r1 = r0 + 8;
#pragma unroll
            for (int nf = 0; nf < 6; nf++) {
                int cl = colBase + nf * 8 + tig * 2;
                float bv0 = b1[nBase + cl], bv1 = b1[nBase + cl + 1];
                float* u0 = g_U + (size_t)(tile * 128 + r0) * 384 + nBase + cl;
                float* u1 = g_U + (size_t)(tile * 128 + r1) * 384 + nBase + cl;
                u0[0] = C[mf][nf][0] + bv0; u0[1] = C[mf][nf][1] + bv1;
                u1[0] = C[mf][nf][2] + bv0; u1[1] = C[mf][nf][3] + bv1;
            }
        }
    }
}

// ---------------- main fused kernel ----------------------------------------
__global__ __launch_bounds__(THREADS, 1)
void fused_mlp_pool(const float* __restrict__ pos,
                    const int*   __restrict__ edges,
                    const float* __restrict__ b2,
                    const float* __restrict__ b3,
                    float* __restrict__ out)
{
    extern __shared__ char smem[];
    __half* sSrc = (__half*)(smem + OFF_SRC);
    __half* sH1  = (__half*)(smem + OFF_H1);
    float*  sU   = (float*)(smem + OFF_U);
    float*  sOm  = (float*)(smem + OFF_OM);
    float*  sH3  = (float*)(smem + OFF_H1);

    const int tile = blockIdx.x;                  // 128 edges per tile
    const int tid  = threadIdx.x;
    const int lane = tid & 31;
    const int wid  = tid >> 5;
    const int rowBase = (wid >> 2) * 32;          // 4 warps in M
    const int colBase = (wid & 3) * 48;           // 4 warps in N

    int stp = 0;
    // L1a chunk-0 weight load ASAP (overlaps embedding)
    stage_chunk(smem, tid, g_Wt1, 384, 0, 0, stp);

    // omega table (replaces per-element exp2f with an LDS)
    if (tid < 32) sOm[tid] = exp2f((float)tid * NLOG);

    // U rows for this tile's 8 dst groups: contiguous, fully coalesced
    for (int i = tid; i < 8 * 384; i += THREADS)
        sU[i] = g_U[(size_t)tile * 3072 + i];
    __syncthreads();   // sOm visible

    // src sincos embeddings -> fp16 sSrc
    for (int i = tid; i < 128 * 96; i += THREADS) {
        int r = i / 96, q = i - r * 96;
        int d = q >> 5, j = q & 31;
        int src = edges[(tile * 128 + r) * 2 + 1];
        float x = pos[src * 3 + d] * sOm[j];
        sSrc[r * 200 + d * 64 + j]      = __float2half(__sinf(x));
        sSrc[r * 200 + d * 64 + 32 + j] = __float2half(__cosf(x));
    }

    float C[2][6][4];
    // Layer 1 (K=192, src half only; sU carries b1 + dst half), two N=192 passes
    mma_core(smem, tid, lane, rowBase, colBase, g_Wt1, 384, 0, 192,
             sSrc, 200, stp, C);
    stp = (stp + 3) & 1;
    stage_chunk(smem, tid, g_Wt1, 384, 192, 0, stp);        // L1b chunk0
    epi_half(lane, rowBase, colBase, C, sU,       384, true, sH1, 392, 0);
    mma_core(smem, tid, lane, rowBase, colBase, g_Wt1, 384, 192, 192,
             sSrc, 200, stp, C);
    stp = (stp + 3) & 1;
    stage_chunk(smem, tid, g_Wt2, 384, 0, 0, stp);          // L2 chunk0
    epi_half(lane, rowBase, colBase, C, sU + 192, 384, true, sH1, 392, 192);
    // Layer 2 (K=384) -> gelu -> h2 into sSrc
    mma_core(smem, tid, lane, rowBase, colBase, g_Wt2, 384, 0, 384,
             sH1, 392, stp, C);
    stp = (stp + 6) & 1;
    stage_chunk(smem, tid, g_Wt3, 192, 0, 0, stp);          // L3 chunk0
    epi_half(lane, rowBase, colBase, C, b2, 0, true, sSrc, 200, 0);
    // Layer 3 (K=192) -> fp32 sH3 (+b3)
    mma_core(smem, tid, lane, rowBase, colBase, g_Wt3, 192, 0, 192,
             sSrc, 200, stp, C);
    {
        const int grp = lane >> 2, tig = lane & 3;
#pragma unroll
        for (int mf = 0; mf < 2; mf++) {
            int r0 = rowBase + mf * 16 + grp;
            int r1 = r0 + 8;
#pragma unroll
            for (int nf = 0; nf < 6; nf++) {
                int cl = colBase + nf * 8 + tig * 2;
                float bv0 = b3[cl], bv1 = b3[cl + 1];
                sH3[r0 * 196 + cl]     = C[mf][nf][0] + bv0;
                sH3[r0 * 196 + cl + 1] = C[mf][nf][1] + bv1;
                sH3[r1 * 196 + cl]     = C[mf][nf][2] + bv0;
                sH3[r1 * 196 + cl + 1] = C[mf][nf][3] + bv1;
            }
        }
    }
    __syncthreads();
    // Segment mean: 8 groups of 16 consecutive rows, /16 (DEG exact)
    for (int i = tid; i < 8 * 192; i += THREADS) {
        int g = i / 192, c = i - g * 192;
        float s = 0.f;
#pragma unroll
        for (int r = 0; r < 16; r++) s += sH3[(g * 16 + r) * 196 + c];
        out[(tile * 8 + g) * 192 + c] = s * 0.0625f;
    }
}

extern "C" void kernel_launch(void* const* d_in, const int* in_sizes, int n_in,
                              void* d_out, int out_size) {
    const float* pos   = (const float*)d_in[0];
    const int*   edges = (const int*)d_in[1];
    // d_in[2] = batch_idx (unused by the reference computation)
    const float* W1 = (const float*)d_in[3];
    const float* b1 = (const float*)d_in[4];
    const float* W2 = (const float*)d_in[5];
    const float* b2 = (const float*)d_in[6];
    const float* W3 = (const float*)d_in[7];
    const float* b3 = (const float*)d_in[8];
    float* out = (float*)d_out;

    const int totalW = 384 * 384 + 192 * 384 + 192 * 192;
    prep_weights<<<(totalW + 255) / 256, 256>>>(W1, W2, W3);

    cudaFuncSetAttribute(dst_proj,
                         cudaFuncAttributeMaxDynamicSharedMemorySize, SMEM_TOTAL);
    dst_proj<<<128, THREADS, SMEM_TOTAL>>>(pos, b1);

    cudaFuncSetAttribute(fused_mlp_pool,
                         cudaFuncAttributeMaxDynamicSharedMemorySize, SMEM_TOTAL);
    fused_mlp_pool<<<2048, THREADS, SMEM_TOTAL>>>(pos, edges, b2, b3, out);
}

// round 16
// speedup vs baseline: 1.5526x; 1.5526x over previous
#include <cuda_runtime.h>
#include <cuda_fp16.h>
#include <stdint.h>

#define THREADS 512

// ---------------- weights (pre-transposed fp16: Wt[n][k], k contiguous) ----
__device__ __half g_Wt1[384 * 384];
__device__ __half g_Wt2[192 * 384];
__device__ __half g_Wt3[192 * 192];
// Precomputed dst projection: U[s][n] = b1[n] + sincos(pos[s]) @ W1_bot
__device__ float g_U[16384 * 384];

__global__ void prep_weights(const float* __restrict__ W1,
                             const float* __restrict__ W2,
                             const float* __restrict__ W3) {
    int idx = blockIdx.x * blockDim.x + threadIdx.x;
    const int N1 = 384 * 384, N2 = 192 * 384, N3 = 192 * 192;
    if (idx < N1) {
        int n = idx / 384, k = idx % 384;
        g_Wt1[idx] = __float2half(W1[k * 384 + n]);
    } else if (idx < N1 + N2) {
        int i = idx - N1;
        int n = i / 384, k = i % 384;
        g_Wt2[i] = __float2half(W2[k * 192 + n]);
    } else if (idx < N1 + N2 + N3) {
        int i = idx - N1 - N2;
        int n = i / 192, k = i % 192;
        g_Wt3[i] = __float2half(W3[k * 192 + n]);
    }
}

// ---------------- smem layout (bytes), 128-edge tile, 1 CTA/SM -------------
//   sSrc : half[128*200]  @ 0        (51200)  src embeds / h2, stride 200
//   sH1  : half[128*392]  @ 51200    (100352) layer1 out, stride 392
//          (float[128*196] overlays this region for layer3 fp32 out)
//   sW   : half[2*192*72] @ 151552   (55296)  double-buffered K=64 W chunks
//   sU   : float[8*384]   @ 206848   (12288)  U rows for this tile's 8 groups
//   sOm  : float[32]      @ 219136   (128)    omega table (one-shot exp2f)
//   sIdx : int[128]       @ 219264   (512)    src node ids (dedup edges LDG)
//   sPos : float[128*4]   @ 219776   (2048)   gathered coords (dedup pos LDG)
// Total 221824 B -> 1 CTA / SM.
// Strides 200/392/72 halves ≡ 4 mod 8 words -> conflict-free ldmatrix.
//
// Stage-buffer PARITY DISCIPLINE: running parity `stp` rotates across passes;
// pass chunk c lives in buffer (stp+c)&1, next pass chunk-0 at (stp+nCh)&1 —
// never the buffer the previous pass's LAST chunk was read from.
#define OFF_SRC 0
#define OFF_H1  51200
#define OFF_W   151552
#define OFF_U   206848
#define OFF_OM  219136
#define OFF_IDX 219264
#define OFF_POS 219776
#define SMEM_TOTAL 221824
#define W_STAGE 13824   // halves per stage buffer (192*72)

__device__ __forceinline__ uint32_t smem_u32(const void* p) {
    return (uint32_t)__cvta_generic_to_shared(p);
}
__device__ __forceinline__ void ldsm_x4(uint32_t r[4], const __half* p) {
    uint32_t a = smem_u32(p);
    asm volatile("ldmatrix.sync.aligned.m8n8.x4.shared.b16 {%0,%1,%2,%3}, [%4];\n"
                 : "=r"(r[0]), "=r"(r[1]), "=r"(r[2]), "=r"(r[3]) : "r"(a));
}
__device__ __forceinline__ void cp16(void* dst, const void* src) {
    uint32_t s = smem_u32(dst);
    asm volatile("cp.async.cg.shared.global [%0], [%1], 16;\n" :: "r"(s), "l"(src));
}
#define CP_COMMIT() asm volatile("cp.async.commit_group;\n")
#define CP_WAIT0()  asm volatile("cp.async.wait_group 0;\n" ::: "memory")

// fast exact gelu: x * Phi(x), Phi via A&S 7.1.25 erf (|err| ~1e-4, << fp16 noise)
__device__ __forceinline__ float gelu1(float x) {
    float q = fabsf(x) * 0.7071067811865476f;
    float t = __fdividef(1.0f, fmaf(0.47047f, q, 1.0f));
    float poly = t * fmaf(t, fmaf(t, 0.7478556f, -0.0958798f), 0.3480242f);
    float E = poly * __expf(-q * q);              // 1 - erf(q), q >= 0
    float phi = (x >= 0.f) ? fmaf(-0.5f, E, 1.0f) : (0.5f * E);
    return x * phi;
}

// Stage one 64-wide K chunk of Wt[nBase..+192)[kc..kc+64) into stage buffer st.
__device__ __forceinline__ void stage_chunk(char* smem, int tid,
                                            const __half* gW, int ldW,
                                            int nBase, int kc, int st) {
    __half* dst = (__half*)(smem + OFF_W) + st * W_STAGE;
    const __half* src = gW + (size_t)nBase * ldW + kc;
#pragma unroll
    for (int it = 0; it < 3; it++) {
        int i = tid + it * THREADS;      // 0..1535 = 192 rows x 8 16B units
        int rw = i >> 3, v = i & 7;
        cp16(dst + rw * 72 + v * 8, src + (size_t)rw * ldW + v * 8);
    }
    CP_COMMIT();
}

// Core GEMM: C[128x192] = A[128xK] @ Wt[nBase..+192)^T.
// Chunk-0 already committed into buffer (stp&1).
// 16 warps as 4x4 grid of 32x48 warp tiles; K=64 chunks, double-buffered.
// EXACT R11 mainloop (ptxas's own schedule beat every manual variant).
__device__ __forceinline__ void mma_core(char* smem, int tid, int lane,
                                         int rowBase, int colBase,
                                         const __half* gW, int ldW, int nBase,
                                         int K, const __half* A, int strideA,
                                         int stp, float (&C)[2][6][4]) {
    const int arow = (lane & 7) + ((lane >> 3) & 1) * 8;
    const int akof = (lane >> 4) * 8;
    const int brow = (lane & 7) + (lane >> 4) * 8;
    const int bkof = ((lane >> 3) & 1) * 8;
    __half* sW = (__half*)(smem + OFF_W);
    const int nCh = K >> 6;
#pragma unroll
    for (int mf = 0; mf < 2; mf++)
#pragma unroll
        for (int nf = 0; nf < 6; nf++)
#pragma unroll
            for (int q = 0; q < 4; q++) C[mf][nf][q] = 0.f;

    for (int c = 0; c < nCh; c++) {
        CP_WAIT0();
        __syncthreads();    // chunk c resident everywhere; all warps done c-1
        if (c + 1 < nCh)
            stage_chunk(smem, tid, gW, ldW, nBase, (c + 1) * 64,
                        (c + 1 + stp) & 1);
        const __half* Wb = sW + ((c + stp) & 1) * W_STAGE;
#pragma unroll
        for (int ks = 0; ks < 4; ks++) {
            int kb = c * 64 + ks * 16;
            uint32_t a[2][4];
#pragma unroll
            for (int mf = 0; mf < 2; mf++)
                ldsm_x4(a[mf], A + (rowBase + mf * 16 + arow) * strideA + kb + akof);
#pragma unroll
            for (int np = 0; np < 3; np++) {
                uint32_t b4[4];
                ldsm_x4(b4, Wb + (colBase + np * 16 + brow) * 72 + ks * 16 + bkof);
#pragma unroll
                for (int h = 0; h < 2; h++) {
                    int nf = np * 2 + h;
#pragma unroll
                    for (int mf = 0; mf < 2; mf++) {
                        asm volatile(
                            "mma.sync.aligned.m16n8k16.row.col.f32.f16.f16.f32 "
                            "{%0,%1,%2,%3}, {%4,%5,%6,%7}, {%8,%9}, {%0,%1,%2,%3};\n"
                            : "+f"(C[mf][nf][0]), "+f"(C[mf][nf][1]),
                              "+f"(C[mf][nf][2]), "+f"(C[mf][nf][3])
                            : "r"(a[mf][0]), "r"(a[mf][1]),
                              "r"(a[mf][2]), "r"(a[mf][3]),
                              "r"(b4[h * 2]), "r"(b4[h * 2 + 1]));
                    }
                }
            }
        }
    }
}

// Epilogue to fp16 smem: out = [gelu](C + bias[(row>>4)*gStride + col]).
__device__ __forceinline__ void epi_half(int lane, int rowBase, int colBase,
                                         float (&C)[2][6][4],
                                         const float* __restrict__ bias,
                                         int gStride, bool doGelu,
                                         __half* outH, int strideOutH,
                                         int outColBase) {
    const int grp = lane >> 2, tig = lane & 3;
#pragma unroll
    for (int mf = 0; mf < 2; mf++) {
        int r0 = rowBase + mf * 16 + grp;
        int r1 = r0 + 8;
        const float* bp = bias + ((rowBase + mf * 16) >> 4) * gStride;
#pragma unroll
        for (int nf = 0; nf < 6; nf++) {
            int cl = colBase + nf * 8 + tig * 2;
            float bv0 = bp[cl], bv1 = bp[cl + 1];
            float v00 = C[mf][nf][0] + bv0;
            float v01 = C[mf][nf][1] + bv1;
            float v10 = C[mf][nf][2] + bv0;
            float v11 = C[mf][nf][3] + bv1;
            if (doGelu) {
                v00 = gelu1(v00); v01 = gelu1(v01);
                v10 = gelu1(v10); v11 = gelu1(v11);
            }
            *(__half2*)(outH + r0 * strideOutH + outColBase + cl) =
                __floats2half2_rn(v00, v01);
            *(__half2*)(outH + r1 * strideOutH + outColBase + cl) =
                __floats2half2_rn(v10, v11);
        }
    }
}

// omega_j = 10000^(-j/32) = 2^(-j*log2(1e4)/32)
#define NLOG (-0.41524101186092033f)

// ---------------- dst projection pre-kernel --------------------------------
// U[s][0..383] = b1 + sincos(pos[s]) @ W1_bot  for s = 0..16383.
// 128 CTAs x 128 rows; same MMA machinery (K=192, two N=192 passes).
__global__ __launch_bounds__(THREADS, 1)
void dst_proj(const float* __restrict__ pos, const float* __restrict__ b1) {
    extern __shared__ char smem[];
    __half* sSrc = (__half*)(smem + OFF_SRC);
    const int tile = blockIdx.x;
    const int tid  = threadIdx.x;
    const int lane = tid & 31;
    const int wid  = tid >> 5;
    const int rowBase = (wid >> 2) * 32;
    const int colBase = (wid & 3) * 48;

    int stp = 0;
    stage_chunk(smem, tid, g_Wt1 + 192, 384, 0, 0, stp);    // W1_bot chunk0

    for (int i = tid; i < 128 * 96; i += THREADS) {
        int r = i / 96, q = i - r * 96;
        int d = q >> 5, j = q & 31;
        int node = tile * 128 + r;
        float x = pos[node * 3 + d] * exp2f((float)j * NLOG);
        sSrc[r * 200 + d * 64 + j]      = __float2half(__sinf(x));
        sSrc[r * 200 + d * 64 + 32 + j] = __float2half(__cosf(x));
    }

    float C[2][6][4];
    const int grp = lane >> 2, tig = lane & 3;
#pragma unroll
    for (int half = 0; half < 2; half++) {
        int nBase = half * 192;
        mma_core(smem, tid, lane, rowBase, colBase, g_Wt1 + 192, 384, nBase,
                 192, sSrc, 200, stp, C);
        stp = (stp + 3) & 1;                   // nCh = 3
        if (half == 0)
            stage_chunk(smem, tid, g_Wt1 + 192, 384, 192, 0, stp);
#pragma unroll
        for (int mf = 0; mf < 2; mf++) {
            int r0 = rowBase + mf * 16 + grp;
            int r1 = r0 + 8;
#pragma unroll
            for (int nf = 0; nf < 6; nf++) {
                int cl = colBase + nf * 8 + tig * 2;
                float bv0 = b1[nBase + cl], bv1 = b1[nBase + cl + 1];
                float* u0 = g_U + (size_t)(tile * 128 + r0) * 384 + nBase + cl;
                float* u1 = g_U + (size_t)(tile * 128 + r1) * 384 + nBase + cl;
                u0[0] = C[mf][nf][0] + bv0; u0[1] = C[mf][nf][1] + bv1;
                u1[0] = C[mf][nf][2] + bv0; u1[1] = C[mf][nf][3] + bv1;
            }
        }
    }
}

// ---------------- main fused kernel ----------------------------------------
__global__ __launch_bounds__(THREADS, 1)
void fused_mlp_pool(const float* __restrict__ pos,
                    const int*   __restrict__ edges,
                    const float* __restrict__ b2,
                    const float* __restrict__ b3,
                    float* __restrict__ out)
{
    extern __shared__ char smem[];
    __half* sSrc = (__half*)(smem + OFF_SRC);
    __half* sH1  = (__half*)(smem + OFF_H1);
    float*  sU   = (float*)(smem + OFF_U);
    float*  sOm  = (float*)(smem + OFF_OM);
    int*    sIdx = (int*)(smem + OFF_IDX);
    float*  sPos = (float*)(smem + OFF_POS);
    float*  sH3  = (float*)(smem + OFF_H1);

    const int tile = blockIdx.x;                  // 128 edges per tile
    const int tid  = threadIdx.x;
    const int lane = tid & 31;
    const int wid  = tid >> 5;
    const int rowBase = (wid >> 2) * 32;          // 4 warps in M
    const int colBase = (wid & 3) * 48;           // 4 warps in N

    int stp = 0;
    // L1a chunk-0 weight load ASAP (overlaps embedding)
    stage_chunk(smem, tid, g_Wt1, 384, 0, 0, stp);

    // omega table (one-shot exp2f) + src node ids (dedup 12K edge LDGs)
    if (tid < 32)  sOm[tid] = exp2f((float)tid * NLOG);
    if (tid < 128) sIdx[tid] = edges[(tile * 128 + tid) * 2 + 1];

    // U rows for this tile's 8 dst groups: contiguous, fully coalesced
    for (int i = tid; i < 8 * 384; i += THREADS)
        sU[i] = g_U[(size_t)tile * 3072 + i];
    __syncthreads();   // sOm, sIdx visible

    // gather coords once (384 LDGs instead of 12K redundant ones)
    if (tid < 384) {
        int r = tid / 3, d = tid - r * 3;
        sPos[r * 4 + d] = pos[(size_t)sIdx[r] * 3 + d];
    }
    __syncthreads();   // sPos visible

    // src sincos embeddings -> fp16 sSrc (pure LDS + MUFU now)
    for (int i = tid; i < 128 * 96; i += THREADS) {
        int r = i / 96, q = i - r * 96;
        int d = q >> 5, j = q & 31;
        float x = sPos[r * 4 + d] * sOm[j];
        sSrc[r * 200 + d * 64 + j]      = __float2half(__sinf(x));
        sSrc[r * 200 + d * 64 + 32 + j] = __float2half(__cosf(x));
    }

    float C[2][6][4];
    // Layer 1 (K=192, src half only; sU carries b1 + dst half), two N=192 passes
    mma_core(smem, tid, lane, rowBase, colBase, g_Wt1, 384, 0, 192,
             sSrc, 200, stp, C);
    stp = (stp + 3) & 1;
    stage_chunk(smem, tid, g_Wt1, 384, 192, 0, stp);        // L1b chunk0
    epi_half(lane, rowBase, colBase, C, sU,       384, true, sH1, 392, 0);
    mma_core(smem, tid, lane, rowBase, colBase, g_Wt1, 384, 192, 192,
             sSrc, 200, stp, C);
    stp = (stp + 3) & 1;
    stage_chunk(smem, tid, g_Wt2, 384, 0, 0, stp);          // L2 chunk0
    epi_half(lane, rowBase, colBase, C, sU + 192, 384, true, sH1, 392, 192);
    // Layer 2 (K=384) -> gelu -> h2 into sSrc
    mma_core(smem, tid, lane, rowBase, colBase, g_Wt2, 384, 0, 384,
             sH1, 392, stp, C);
    stp = (stp + 6) & 1;
    stage_chunk(smem, tid, g_Wt3, 192, 0, 0, stp);          // L3 chunk0
    epi_half(lane, rowBase, colBase, C, b2, 0, true, sSrc, 200, 0);
    // Layer 3 (K=192) -> fp32 sH3 (+b3)
    mma_core(smem, tid, lane, rowBase, colBase, g_Wt3, 192, 0, 192,
             sSrc, 200, stp, C);
    {
        const int grp = lane >> 2, tig = lane & 3;
#pragma unroll
        for (int mf = 0; mf < 2; mf++) {
            int r0 = rowBase + mf * 16 + grp;
            int r1 = r0 + 8;
#pragma unroll
            for (int nf = 0; nf < 6; nf++) {
                int cl = colBase + nf * 8 + tig * 2;
                float bv0 = b3[cl], bv1 = b3[cl + 1];
                sH3[r0 * 196 + cl]     = C[mf][nf][0] + bv0;
                sH3[r0 * 196 + cl + 1] = C[mf][nf][1] + bv1;
                sH3[r1 * 196 + cl]     = C[mf][nf][2] + bv0;
                sH3[r1 * 196 + cl + 1] = C[mf][nf][3] + bv1;
            }
        }
    }
    __syncthreads();
    // Segment mean: 8 groups of 16 consecutive rows, /16 (DEG exact)
    for (int i = tid; i < 8 * 192; i += THREADS) {
        int g = i / 192, c = i - g * 192;
        float s = 0.f;
#pragma unroll
        for (int r = 0; r < 16; r++) s += sH3[(g * 16 + r) * 196 + c];
        out[(tile * 8 + g) * 192 + c] = s * 0.0625f;
    }
}

extern "C" void kernel_launch(void* const* d_in, const int* in_sizes, int n_in,
                              void* d_out, int out_size) {
    const float* pos   = (const float*)d_in[0];
    const int*   edges = (const int*)d_in[1];
    // d_in[2] = batch_idx (unused by the reference computation)
    const float* W1 = (const float*)d_in[3];
    const float* b1 = (const float*)d_in[4];
    const float* W2 = (const float*)d_in[5];
    const float* b2 = (const float*)d_in[6];
    const float* W3 = (const float*)d_in[7];
    const float* b3 = (const float*)d_in[8];
    float* out = (float*)d_out;

    const int totalW = 384 * 384 + 192 * 384 + 192 * 192;
    prep_weights<<<(totalW + 255) / 256, 256>>>(W1, W2, W3);

    cudaFuncSetAttribute(dst_proj,
                         cudaFuncAttributeMaxDynamicSharedMemorySize, SMEM_TOTAL);
    dst_proj<<<128, THREADS, SMEM_TOTAL>>>(pos, b1);

    cudaFuncSetAttribute(fused_mlp_pool,
                         cudaFuncAttributeMaxDynamicSharedMemorySize, SMEM_TOTAL);
    fused_mlp_pool<<<2048, THREADS, SMEM_TOTAL>>>(pos, edges, b2, b3, out);
}

// round 17
// speedup vs baseline: 1.5685x; 1.0102x over previous
#include <cuda_runtime.h>
#include <cuda_fp16.h>
#include <stdint.h>

#define THREADS 512

// ---------------- weights (pre-transposed fp16: Wt[n][k], k contiguous) ----
__device__ __half g_Wt1[384 * 384];
__device__ __half g_Wt2[192 * 384];
__device__ __half g_Wt3[192 * 192];
// Precomputed dst projection: U[s][n] = b1[n] + sincos(pos[s]) @ W1_bot
__device__ float g_U[16384 * 384];

__global__ void prep_weights(const float* __restrict__ W1,
                             const float* __restrict__ W2,
                             const float* __restrict__ W3) {
    int idx = blockIdx.x * blockDim.x + threadIdx.x;
    const int N1 = 384 * 384, N2 = 192 * 384, N3 = 192 * 192;
    if (idx < N1) {
        int n = idx / 384, k = idx % 384;
        g_Wt1[idx] = __float2half(W1[k * 384 + n]);
    } else if (idx < N1 + N2) {
        int i = idx - N1;
        int n = i / 384, k = i % 384;
        g_Wt2[i] = __float2half(W2[k * 192 + n]);
    } else if (idx < N1 + N2 + N3) {
        int i = idx - N1 - N2;
        int n = i / 192, k = i % 192;
        g_Wt3[i] = __float2half(W3[k * 192 + n]);
    }
}

// ---------------- smem layout (bytes), 128-edge tile, 1 CTA/SM -------------
// Same as R16. W stage buffers are PARTITIONED by column group: group g owns
// rows [g*48, (g+1)*48) of both buffers and syncs with bar.sync g+1, 128.
#define OFF_SRC 0
#define OFF_H1  51200
#define OFF_W   151552
#define OFF_U   206848
#define OFF_OM  219136
#define OFF_IDX 219264
#define OFF_POS 219776
#define SMEM_TOTAL 221824
#define W_STAGE 13824   // halves per stage buffer (192*72)

__device__ __forceinline__ uint32_t smem_u32(const void* p) {
    return (uint32_t)__cvta_generic_to_shared(p);
}
__device__ __forceinline__ void ldsm_x4(uint32_t r[4], const __half* p) {
    uint32_t a = smem_u32(p);
    asm volatile("ldmatrix.sync.aligned.m8n8.x4.shared.b16 {%0,%1,%2,%3}, [%4];\n"
                 : "=r"(r[0]), "=r"(r[1]), "=r"(r[2]), "=r"(r[3]) : "r"(a));
}
__device__ __forceinline__ void cp16(void* dst, const void* src) {
    uint32_t s = smem_u32(dst);
    asm volatile("cp.async.cg.shared.global [%0], [%1], 16;\n" :: "r"(s), "l"(src));
}
#define CP_COMMIT() asm volatile("cp.async.commit_group;\n")
#define CP_WAIT0()  asm volatile("cp.async.wait_group 0;\n" ::: "memory")
// Group-scoped barrier: 4 warps (128 threads) of column group g use id g+1.
#define BAR_GRP(g) asm volatile("bar.sync %0, 128;\n" :: "r"((g) + 1) : "memory")

// fast exact gelu: x * Phi(x), Phi via A&S 7.1.25 erf (|err| ~1e-4, << fp16 noise)
__device__ __forceinline__ float gelu1(float x) {
    float q = fabsf(x) * 0.7071067811865476f;
    float t = __fdividef(1.0f, fmaf(0.47047f, q, 1.0f));
    float poly = t * fmaf(t, fmaf(t, 0.7478556f, -0.0958798f), 0.3480242f);
    float E = poly * __expf(-q * q);              // 1 - erf(q), q >= 0
    float phi = (x >= 0.f) ? fmaf(-0.5f, E, 1.0f) : (0.5f * E);
    return x * phi;
}

// Group-scoped staging: group g stages ITS 48 rows of the 64-wide K chunk.
// 48 rows x 8 units = 384 cp16 over 128 threads = 3 each.
__device__ __forceinline__ void stage_chunk_grp(char* smem, int colGrp,
                                                int grpTid,
                                                const __half* gW, int ldW,
                                                int nBase, int kc, int st) {
    __half* dst = (__half*)(smem + OFF_W) + st * W_STAGE;
    const __half* src = gW + (size_t)nBase * ldW + kc;
#pragma unroll
    for (int it = 0; it < 3; it++) {
        int u = grpTid + it * 128;           // 0..383
        int rw = colGrp * 48 + (u >> 3), v = u & 7;
        cp16(dst + rw * 72 + v * 8, src + (size_t)rw * ldW + v * 8);
    }
    CP_COMMIT();
}

// Core GEMM: C[128x192] = A[128xK] @ Wt[nBase..+192)^T.
// Chunk-0 already committed (group-scoped) into buffer (stp&1).
// 16 warps as 4x4 grid of 32x48 warp tiles. Column groups run DECOUPLED:
// each group stages its own W rows and syncs on a 128-thread named barrier,
// so the 4 groups drift out of phase and overlap LDSM with HMMA naturally.
// PRECONDITION: A is stable (full-CTA sync before the pass if A changed).
__device__ __forceinline__ void mma_core(char* smem, int colGrp, int grpTid,
                                         int lane,
                                         int rowBase, int colBase,
                                         const __half* gW, int ldW, int nBase,
                                         int K, const __half* A, int strideA,
                                         int stp, float (&C)[2][6][4]) {
    const int arow = (lane & 7) + ((lane >> 3) & 1) * 8;
    const int akof = (lane >> 4) * 8;
    const int brow = (lane & 7) + (lane >> 4) * 8;
    const int bkof = ((lane >> 3) & 1) * 8;
    __half* sW = (__half*)(smem + OFF_W);
    const int nCh = K >> 6;
#pragma unroll
    for (int mf = 0; mf < 2; mf++)
#pragma unroll
        for (int nf = 0; nf < 6; nf++)
#pragma unroll
            for (int q = 0; q < 4; q++) C[mf][nf][q] = 0.f;

    for (int c = 0; c < nCh; c++) {
        CP_WAIT0();
        BAR_GRP(colGrp);   // group's chunk c resident; group done with c-1
        if (c + 1 < nCh)
            stage_chunk_grp(smem, colGrp, grpTid, gW, ldW, nBase,
                            (c + 1) * 64, (c + 1 + stp) & 1);
        const __half* Wb = sW + ((c + stp) & 1) * W_STAGE;
#pragma unroll
        for (int ks = 0; ks < 4; ks++) {
            int kb = c * 64 + ks * 16;
            uint32_t a[2][4];
#pragma unroll
            for (int mf = 0; mf < 2; mf++)
                ldsm_x4(a[mf], A + (rowBase + mf * 16 + arow) * strideA + kb + akof);
#pragma unroll
            for (int np = 0; np < 3; np++) {
                uint32_t b4[4];
                ldsm_x4(b4, Wb + (colBase + np * 16 + brow) * 72 + ks * 16 + bkof);
#pragma unroll
                for (int h = 0; h < 2; h++) {
                    int nf = np * 2 + h;
#pragma unroll
                    for (int mf = 0; mf < 2; mf++) {
                        asm volatile(
                            "mma.sync.aligned.m16n8k16.row.col.f32.f16.f16.f32 "
                            "{%0,%1,%2,%3}, {%4,%5,%6,%7}, {%8,%9}, {%0,%1,%2,%3};\n"
                            : "+f"(C[mf][nf][0]), "+f"(C[mf][nf][1]),
                              "+f"(C[mf][nf][2]), "+f"(C[mf][nf][3])
                            : "r"(a[mf][0]), "r"(a[mf][1]),
                              "r"(a[mf][2]), "r"(a[mf][3]),
                              "r"(b4[h * 2]), "r"(b4[h * 2 + 1]));
                    }
                }
            }
        }
    }
}

// Epilogue to fp16 smem: out = [gelu](C + bias[(row>>4)*gStride + col]).
__device__ __forceinline__ void epi_half(int lane, int rowBase, int colBase,
                                         float (&C)[2][6][4],
                                         const float* __restrict__ bias,
                                         int gStride, bool doGelu,
                                         __half* outH, int strideOutH,
                                         int outColBase) {
    const int grp = lane >> 2, tig = lane & 3;
#pragma unroll
    for (int mf = 0; mf < 2; mf++) {
        int r0 = rowBase + mf * 16 + grp;
        int r1 = r0 + 8;
        const float* bp = bias + ((rowBase + mf * 16) >> 4) * gStride;
#pragma unroll
        for (int nf = 0; nf < 6; nf++) {
            int cl = colBase + nf * 8 + tig * 2;
            float bv0 = bp[cl], bv1 = bp[cl + 1];
            float v00 = C[mf][nf][0] + bv0;
            float v01 = C[mf][nf][1] + bv1;
            float v10 = C[mf][nf][2] + bv0;
            float v11 = C[mf][nf][3] + bv1;
            if (doGelu) {
                v00 = gelu1(v00); v01 = gelu1(v01);
                v10 = gelu1(v10); v11 = gelu1(v11);
            }
            *(__half2*)(outH + r0 * strideOutH + outColBase + cl) =
                __floats2half2_rn(v00, v01);
            *(__half2*)(outH + r1 * strideOutH + outColBase + cl) =
                __floats2half2_rn(v10, v11);
        }
    }
}

// omega_j = 10000^(-j/32) = 2^(-j*log2(1e4)/32)
#define NLOG (-0.41524101186092033f)

// ---------------- dst projection pre-kernel --------------------------------
// U[s][0..383] = b1 + sincos(pos[s]) @ W1_bot  for s = 0..16383.
// 128 CTAs x 128 rows; same group-decoupled MMA machinery.
__global__ __launch_bounds__(THREADS, 1)
void dst_proj(const float* __restrict__ pos, const float* __restrict__ b1) {
    extern __shared__ char smem[];
    __half* sSrc = (__half*)(smem + OFF_SRC);
    const int tile = blockIdx.x;
    const int tid  = threadIdx.x;
    const int lane = tid & 31;
    const int wid  = tid >> 5;
    const int rowBase = (wid >> 2) * 32;
    const int colBase = (wid & 3) * 48;
    const int colGrp  = wid & 3;
    const int grpTid  = ((wid >> 2) << 5) + lane;

    int stp = 0;
    stage_chunk_grp(smem, colGrp, grpTid, g_Wt1 + 192, 384, 0, 0, stp);

    for (int i = tid; i < 128 * 96; i += THREADS) {
        int r = i / 96, q = i - r * 96;
        int d = q >> 5, j = q & 31;
        int node = tile * 128 + r;
        float x = pos[node * 3 + d] * exp2f((float)j * NLOG);
        sSrc[r * 200 + d * 64 + j]      = __float2half(__sinf(x));
        sSrc[r * 200 + d * 64 + 32 + j] = __float2half(__cosf(x));
    }
    __syncthreads();   // sSrc (A) stable before decoupled groups read it

    float C[2][6][4];
    const int grp = lane >> 2, tig = lane & 3;
#pragma unroll
    for (int half = 0; half < 2; half++) {
        int nBase = half * 192;
        mma_core(smem, colGrp, grpTid, lane, rowBase, colBase,
                 g_Wt1 + 192, 384, nBase, 192, sSrc, 200, stp, C);
        stp = (stp + 3) & 1;                   // nCh = 3
        if (half == 0)
            stage_chunk_grp(smem, colGrp, grpTid, g_Wt1 + 192, 384, 192, 0, stp);
#pragma unroll
        for (int mf = 0; mf < 2; mf++) {
            int r0 = rowBase + mf * 16 + grp;
            int r1 = r0 + 8;
#pragma unroll
            for (int nf = 0; nf < 6; nf++) {
                int cl = colBase + nf * 8 + tig * 2;
                float bv0 = b1[nBase + cl], bv1 = b1[nBase + cl + 1];
                float* u0 = g_U + (size_t)(tile * 128 + r0) * 384 + nBase + cl;
                float* u1 = g_U + (size_t)(tile * 128 + r1) * 384 + nBase + cl;
                u0[0] = C[mf][nf][0] + bv0; u0[1] = C[mf][nf][1] + bv1;
                u1[0] = C[mf][nf][2] + bv0; u1[1] = C[mf][nf][3] + bv1;
            }
        }
    }
}

// ---------------- main fused kernel ----------------------------------------
__global__ __launch_bounds__(THREADS, 1)
void fused_mlp_pool(const float* __restrict__ pos,
                    const int*   __restrict__ edges,
                    const float* __restrict__ b2,
                    const float* __restrict__ b3,
                    float* __restrict__ out)
{
    extern __shared__ char smem[];
    __half* sSrc = (__half*)(smem + OFF_SRC);
    __half* sH1  = (__half*)(smem + OFF_H1);
    float*  sU   = (float*)(smem + OFF_U);
    float*  sOm  = (float*)(smem + OFF_OM);
    int*    sIdx = (int*)(smem + OFF_IDX);
    float*  sPos = (float*)(smem + OFF_POS);
    float*  sH3  = (float*)(smem + OFF_H1);

    const int tile = blockIdx.x;                  // 128 edges per tile
    const int tid  = threadIdx.x;
    const int lane = tid & 31;
    const int wid  = tid >> 5;
    const int rowBase = (wid >> 2) * 32;          // 4 warps in M
    const int colBase = (wid & 3) * 48;           // 4 warps in N
    const int colGrp  = wid & 3;
    const int grpTid  = ((wid >> 2) << 5) + lane;

    int stp = 0;
    // L1a chunk-0 weight load ASAP (group-scoped; overlaps embedding)
    stage_chunk_grp(smem, colGrp, grpTid, g_Wt1, 384, 0, 0, stp);

    // omega table (one-shot exp2f) + src node ids (dedup 12K edge LDGs)
    if (tid < 32)  sOm[tid] = exp2f((float)tid * NLOG);
    if (tid < 128) sIdx[tid] = edges[(tile * 128 + tid) * 2 + 1];

    // U rows for this tile's 8 dst groups: contiguous, fully coalesced
    for (int i = tid; i < 8 * 384; i += THREADS)
        sU[i] = g_U[(size_t)tile * 3072 + i];
    __syncthreads();   // sOm, sIdx visible

    // gather coords once (384 LDGs instead of 12K redundant ones)
    if (tid < 384) {
        int r = tid / 3, d = tid - r * 3;
        sPos[r * 4 + d] = pos[(size_t)sIdx[r] * 3 + d];
    }
    __syncthreads();   // sPos visible

    // src sincos embeddings -> fp16 sSrc (pure LDS + MUFU)
    for (int i = tid; i < 128 * 96; i += THREADS) {
        int r = i / 96, q = i - r * 96;
        int d = q >> 5, j = q & 31;
        float x = sPos[r * 4 + d] * sOm[j];
        sSrc[r * 200 + d * 64 + j]      = __float2half(__sinf(x));
        sSrc[r * 200 + d * 64 + 32 + j] = __float2half(__cosf(x));
    }
    __syncthreads();   // sSrc + sU stable -> groups may decouple from here

    float C[2][6][4];
    // Layer 1 (K=192, src half only; sU carries b1 + dst half), two N=192 passes
    // (no full sync between L1a/L1b: both read only sSrc; epilogues write sH1)
    mma_core(smem, colGrp, grpTid, lane, rowBase, colBase, g_Wt1, 384, 0, 192,
             sSrc, 200, stp, C);
    stp = (stp + 3) & 1;
    stage_chunk_grp(smem, colGrp, grpTid, g_Wt1, 384, 192, 0, stp);  // L1b ch0
    epi_half(lane, rowBase, colBase, C, sU,       384, true, sH1, 392, 0);
    mma_core(smem, colGrp, grpTid, lane, rowBase, colBase, g_Wt1, 384, 192, 192,
             sSrc, 200, stp, C);
    stp = (stp + 3) & 1;
    stage_chunk_grp(smem, colGrp, grpTid, g_Wt2, 384, 0, 0, stp);    // L2 ch0
    epi_half(lane, rowBase, colBase, C, sU + 192, 384, true, sH1, 392, 192);
    __syncthreads();   // ALL groups' h1 written before anyone reads sH1
    // Layer 2 (K=384) -> gelu -> h2 into sSrc
    mma_core(smem, colGrp, grpTid, lane, rowBase, colBase, g_Wt2, 384, 0, 384,
             sH1, 392, stp, C);
    stp = (stp + 6) & 1;
    stage_chunk_grp(smem, colGrp, grpTid, g_Wt3, 192, 0, 0, stp);    // L3 ch0
    epi_half(lane, rowBase, colBase, C, b2, 0, true, sSrc, 200, 0);
    __syncthreads();   // ALL groups' h2 written before anyone reads sSrc
    // Layer 3 (K=192) -> fp32 sH3 (+b3)
    mma_core(smem, colGrp, grpTid, lane, rowBase, colBase, g_Wt3, 192, 0, 192,
             sSrc, 200, stp, C);
    {
        const int grp = lane >> 2, tig = lane & 3;
#pragma unroll
        for (int mf = 0; mf < 2; mf++) {
            int r0 = rowBase + mf * 16 + grp;
            int r1 = r0 + 8;
#pragma unroll
            for (int nf = 0; nf < 6; nf++) {
                int cl = colBase + nf * 8 + tig * 2;
                float bv0 = b3[cl], bv1 = b3[cl + 1];
                sH3[r0 * 196 + cl]     = C[mf][nf][0] + bv0;
                sH3[r0 * 196 + cl + 1] = C[mf][nf][1] + bv1;
                sH3[r1 * 196 + cl]     = C[mf][nf][2] + bv0;
                sH3[r1 * 196 + cl + 1] = C[mf][nf][3] + bv1;
            }
        }
    }
    __syncthreads();
    // Segment mean: 8 groups of 16 consecutive rows, /16 (DEG exact)
    for (int i = tid; i < 8 * 192; i += THREADS) {
        int g = i / 192, c = i - g * 192;
        float s = 0.f;
#pragma unroll
        for (int r = 0; r < 16; r++) s += sH3[(g * 16 + r) * 196 + c];
        out[(tile * 8 + g) * 192 + c] = s * 0.0625f;
    }
}

extern "C" void kernel_launch(void* const* d_in, const int* in_sizes, int n_in,
                              void* d_out, int out_size) {
    const float* pos   = (const float*)d_in[0];
    const int*   edges = (const int*)d_in[1];
    // d_in[2] = batch_idx (unused by the reference computation)
    const float* W1 = (const float*)d_in[3];
    const float* b1 = (const float*)d_in[4];
    const float* W2 = (const float*)d_in[5];
    const float* b2 = (const float*)d_in[6];
    const float* W3 = (const float*)d_in[7];
    const float* b3 = (const float*)d_in[8];
    float* out = (float*)d_out;

    const int totalW = 384 * 384 + 192 * 384 + 192 * 192;
    prep_weights<<<(totalW + 255) / 256, 256>>>(W1, W2, W3);

    cudaFuncSetAttribute(dst_proj,
                         cudaFuncAttributeMaxDynamicSharedMemorySize, SMEM_TOTAL);
    dst_proj<<<128, THREADS, SMEM_TOTAL>>>(pos, b1);

    cudaFuncSetAttribute(fused_mlp_pool,
                         cudaFuncAttributeMaxDynamicSharedMemorySize, SMEM_TOTAL);
    fused_mlp_pool<<<2048, THREADS, SMEM_TOTAL>>>(pos, edges, b2, b3, out);
}